// round 6
// baseline (speedup 1.0000x reference)
#include <cuda_runtime.h>
#include <cuda_bf16.h>
#include <cstdint>
#include <math.h>

// Problem constants
#define KB 64      // batch
#define KT 512     // time
#define KD 512     // input dim
#define KH 2048    // hidden
#define KO 7       // output
#define KG4 8192   // 4*KH
#define KBT 32768  // KB*KT

// ---------------------------------------------------------------------------
// Device-global scratch (allocation-free per harness rules)
// ---------------------------------------------------------------------------
__device__ __align__(256) __nv_bfloat16 g_Xhi[KBT * KD];
__device__ __align__(256) __nv_bfloat16 g_Xlo[KBT * KD];
__device__ __align__(256) __nv_bfloat16 g_Wih_hi[KG4 * KD];
__device__ __align__(256) __nv_bfloat16 g_Wih_lo[KG4 * KD];
__device__ __align__(256) __nv_bfloat16 g_Whh_hi[(size_t)KG4 * KH];
__device__ __align__(256) __nv_bfloat16 g_Whh_lo[(size_t)KG4 * KH];
__device__ __align__(256) float g_Xg[(size_t)KBT * KG4];     // 1 GiB: x@W_ih^T + b_ih + b_hh
__device__ __align__(256) float g_meanx[KB * KD];
__device__ __align__(256) float g_c[KB * KH];
__device__ __align__(256) __nv_bfloat16 g_hhi[2][KB * KH];   // ping-pong split h
__device__ __align__(256) __nv_bfloat16 g_hlo[2][KB * KH];
__device__ __align__(256) float g_hs[(size_t)KT * KB * KH];  // 256 MB: all h states

// ---------------------------------------------------------------------------
// mma.sync m16n8k16 bf16 (fp32 accumulate)
// ---------------------------------------------------------------------------
__device__ __forceinline__ void mma16816(float* c,
    uint32_t a0, uint32_t a1, uint32_t a2, uint32_t a3,
    uint32_t b0, uint32_t b1) {
  asm volatile(
    "mma.sync.aligned.m16n8k16.row.col.f32.bf16.bf16.f32 "
    "{%0,%1,%2,%3}, {%4,%5,%6,%7}, {%8,%9}, {%0,%1,%2,%3};\n"
    : "+f"(c[0]), "+f"(c[1]), "+f"(c[2]), "+f"(c[3])
    : "r"(a0), "r"(a1), "r"(a2), "r"(a3), "r"(b0), "r"(b1));
}

__device__ __forceinline__ void split2(float a, __nv_bfloat16& hi, __nv_bfloat16& lo) {
  hi = __float2bfloat16(a);
  lo = __float2bfloat16(a - __bfloat162float(hi));
}

// cp.async 16B, L1-bypass (data is L2-resident streaming)
__device__ __forceinline__ void cpa16(void* dst_smem, const void* src_gmem) {
  uint32_t s = (uint32_t)__cvta_generic_to_shared(dst_smem);
  asm volatile("cp.async.cg.shared.global [%0], [%1], 16;\n" :: "r"(s), "l"(src_gmem));
}
#define CP_COMMIT() asm volatile("cp.async.commit_group;\n" ::: "memory")
#define CP_WAIT1()  asm volatile("cp.async.wait_group 1;\n" ::: "memory")
#define CP_WAIT0()  asm volatile("cp.async.wait_group 0;\n" ::: "memory")

// ---------------------------------------------------------------------------
// bf16 hi/lo split kernels
// ---------------------------------------------------------------------------
__global__ void split_x_kernel(const float* __restrict__ in) {
  int i = blockIdx.x * 256 + threadIdx.x;   // grid covers exactly KBT*KD
  __nv_bfloat16 h, l; split2(in[i], h, l);
  g_Xhi[i] = h; g_Xlo[i] = l;
}
__global__ void split_wih_kernel(const float* __restrict__ in) {
  int i = blockIdx.x * 256 + threadIdx.x;   // KG4*KD
  __nv_bfloat16 h, l; split2(in[i], h, l);
  g_Wih_hi[i] = h; g_Wih_lo[i] = l;
}
__global__ void split_whh_kernel(const float* __restrict__ in) {
  int i = blockIdx.x * 256 + threadIdx.x;   // KG4*KH
  __nv_bfloat16 h, l; split2(in[i], h, l);
  g_Whh_hi[i] = h; g_Whh_lo[i] = l;
}

// ---------------------------------------------------------------------------
// mean over time
// ---------------------------------------------------------------------------
__global__ void mean_kernel(const float* __restrict__ x) {
  int d = blockIdx.x * 256 + threadIdx.x;   // grid (KD/256, KB)
  int b = blockIdx.y;
  const float* p = x + (size_t)b * KT * KD + d;
  float s = 0.f;
  for (int t = 0; t < KT; t++) s += p[(size_t)t * KD];
  g_meanx[b * KD + d] = s * (1.0f / KT);
}

// ---------------------------------------------------------------------------
// h0 = mean_x @ W_h0^T + b_h0 ; c0 likewise. Writes c and split-h buffer 0.
// ---------------------------------------------------------------------------
__global__ void init_kernel(const float* __restrict__ Wh0, const float* __restrict__ bh0,
                            const float* __restrict__ Wc0, const float* __restrict__ bc0) {
  int j = blockIdx.x * 256 + threadIdx.x;   // grid (KH/256, KB)
  int b = blockIdx.y;
  const float* m  = g_meanx + b * KD;
  const float* wh = Wh0 + (size_t)j * KD;
  const float* wc = Wc0 + (size_t)j * KD;
  float sh = 0.f, sc = 0.f;
  for (int k = 0; k < KD; k++) { float mv = m[k]; sh += mv * wh[k]; sc += mv * wc[k]; }
  sh += bh0[j]; sc += bc0[j];
  int idx = b * KH + j;
  g_c[idx] = sc;
  __nv_bfloat16 h, l; split2(sh, h, l);
  g_hhi[0][idx] = h; g_hlo[0][idx] = l;
}

// ---------------------------------------------------------------------------
// Xg = X @ W_ih^T + (b_ih + b_hh)   via bf16x3 split mma
// CTA tile 128(M) x 64(N), K = 512 in chunks of 32. 256 threads, warps 4x2.
// 32768 CTAs -> multi-CTA/SM overlap hides load latency; no pipeline needed.
// ---------------------------------------------------------------------------
#define XG_AS 40   // smem row stride in bf16 (80B: 16B-aligned, conflict-free frags)
__global__ void __launch_bounds__(256) xg_gemm_kernel(const float* __restrict__ b_ih,
                                                      const float* __restrict__ b_hh) {
  __shared__ __align__(16) __nv_bfloat16 sAhi[128 * XG_AS];
  __shared__ __align__(16) __nv_bfloat16 sAlo[128 * XG_AS];
  __shared__ __align__(16) __nv_bfloat16 sBhi[64 * XG_AS];
  __shared__ __align__(16) __nv_bfloat16 sBlo[64 * XG_AS];
  const int tid = threadIdx.x, lane = tid & 31, w = tid >> 5;
  const int wm = w >> 1, wn = w & 1;              // warp tile: rows 32*wm, cols 32*wn
  const int m0 = blockIdx.y * 128, n0 = blockIdx.x * 64;
  const int g = lane >> 2, tt = lane & 3;

  float acc[2][4][4];
  #pragma unroll
  for (int a = 0; a < 2; a++)
    #pragma unroll
    for (int b = 0; b < 4; b++)
      #pragma unroll
      for (int c = 0; c < 4; c++) acc[a][b][c] = 0.f;

  for (int k0 = 0; k0 < KD; k0 += 32) {
    #pragma unroll
    for (int i = 0; i < 2; i++) {
      int id = tid + i * 256;                     // 0..511
      int r = id >> 2, c4 = id & 3;               // 4 uint4 per 32-col row
      *reinterpret_cast<uint4*>(&sAhi[r * XG_AS + c4 * 8]) =
        reinterpret_cast<const uint4*>(g_Xhi + (size_t)(m0 + r) * KD + k0)[c4];
      *reinterpret_cast<uint4*>(&sAlo[r * XG_AS + c4 * 8]) =
        reinterpret_cast<const uint4*>(g_Xlo + (size_t)(m0 + r) * KD + k0)[c4];
    }
    {
      int r = tid >> 2, c4 = tid & 3;             // 64 rows x 4 uint4 = 256
      *reinterpret_cast<uint4*>(&sBhi[r * XG_AS + c4 * 8]) =
        reinterpret_cast<const uint4*>(g_Wih_hi + (size_t)(n0 + r) * KD + k0)[c4];
      *reinterpret_cast<uint4*>(&sBlo[r * XG_AS + c4 * 8]) =
        reinterpret_cast<const uint4*>(g_Wih_lo + (size_t)(n0 + r) * KD + k0)[c4];
    }
    __syncthreads();
    #pragma unroll
    for (int kk = 0; kk < 32; kk += 16) {
      uint32_t Ah[2][4], Al[2][4], Bh[4][2], Bl[4][2];
      #pragma unroll
      for (int mt = 0; mt < 2; mt++) {
        const __nv_bfloat16* pa = sAhi + (wm * 32 + mt * 16 + g) * XG_AS + kk + 2 * tt;
        const __nv_bfloat16* pl = sAlo + (wm * 32 + mt * 16 + g) * XG_AS + kk + 2 * tt;
        Ah[mt][0] = *(const uint32_t*)(pa);
        Ah[mt][1] = *(const uint32_t*)(pa + 8 * XG_AS);
        Ah[mt][2] = *(const uint32_t*)(pa + 8);
        Ah[mt][3] = *(const uint32_t*)(pa + 8 * XG_AS + 8);
        Al[mt][0] = *(const uint32_t*)(pl);
        Al[mt][1] = *(const uint32_t*)(pl + 8 * XG_AS);
        Al[mt][2] = *(const uint32_t*)(pl + 8);
        Al[mt][3] = *(const uint32_t*)(pl + 8 * XG_AS + 8);
      }
      #pragma unroll
      for (int nt = 0; nt < 4; nt++) {
        const __nv_bfloat16* pb = sBhi + (wn * 32 + nt * 8 + g) * XG_AS + kk + 2 * tt;
        const __nv_bfloat16* pq = sBlo + (wn * 32 + nt * 8 + g) * XG_AS + kk + 2 * tt;
        Bh[nt][0] = *(const uint32_t*)(pb);
        Bh[nt][1] = *(const uint32_t*)(pb + 8);
        Bl[nt][0] = *(const uint32_t*)(pq);
        Bl[nt][1] = *(const uint32_t*)(pq + 8);
      }
      #pragma unroll
      for (int mt = 0; mt < 2; mt++)
        #pragma unroll
        for (int nt = 0; nt < 4; nt++) {
          mma16816(acc[mt][nt], Ah[mt][0], Ah[mt][1], Ah[mt][2], Ah[mt][3], Bh[nt][0], Bh[nt][1]);
          mma16816(acc[mt][nt], Ah[mt][0], Ah[mt][1], Ah[mt][2], Ah[mt][3], Bl[nt][0], Bl[nt][1]);
          mma16816(acc[mt][nt], Al[mt][0], Al[mt][1], Al[mt][2], Al[mt][3], Bh[nt][0], Bh[nt][1]);
        }
    }
    __syncthreads();
  }
  // epilogue: add fused biases, store fp32 Xg
  #pragma unroll
  for (int mt = 0; mt < 2; mt++)
    #pragma unroll
    for (int nt = 0; nt < 4; nt++) {
      int row = m0 + wm * 32 + mt * 16 + g;
      int col = n0 + wn * 32 + nt * 8 + 2 * tt;
      float bs0 = b_ih[col] + b_hh[col];
      float bs1 = b_ih[col + 1] + b_hh[col + 1];
      size_t o0 = (size_t)row * KG4 + col;
      g_Xg[o0]     = acc[mt][nt][0] + bs0;
      g_Xg[o0 + 1] = acc[mt][nt][1] + bs1;
      g_Xg[o0 + (size_t)8 * KG4]     = acc[mt][nt][2] + bs0;
      g_Xg[o0 + (size_t)8 * KG4 + 1] = acc[mt][nt][3] + bs1;
    }
}

// ---------------------------------------------------------------------------
// One LSTM step: gates[64, tile] = Xg[t] + h_prev @ W_hh^T, fused cell update.
// Grid 128 CTAs: CTA n owns hidden cols [n*16, n*16+16) across all 4 gates.
// Logical gate tile per CTA: 64(batch) x 64 (4 quadrants x 16), K=2048.
// 256 threads: warps 2(M) x 4(N-quadrant).
// 2-stage cp.async pipeline, K-chunk 32 (static smem: 2 x 20480 B).
// ---------------------------------------------------------------------------
#define ST_AS 40                       // smem row stride bf16: 80B, conflict-free
#define STAGE_B (4 * 64 * ST_AS * 2)   // 20480 B per stage (Ahi,Alo,Bhi,Blo)
__global__ void __launch_bounds__(256) lstm_step_kernel(int t) {
  __shared__ __align__(16) char smem_raw[2 * STAGE_B];   // 40960 B

  const int tid = threadIdx.x, lane = tid & 31, w = tid >> 5;
  const int wm = w & 1;        // 0..1 -> batch rows 32*wm
  const int wn = w >> 1;       // 0..3 -> gate quadrant (i,f,g,o)
  const int n = blockIdx.x;
  const int hc0 = n * 16;
  const int p = t & 1;
  const __nv_bfloat16* __restrict__ hi_in = g_hhi[p];
  const __nv_bfloat16* __restrict__ lo_in = g_hlo[p];
  __nv_bfloat16* __restrict__ hi_out = g_hhi[p ^ 1];
  __nv_bfloat16* __restrict__ lo_out = g_hlo[p ^ 1];

  const int g = lane >> 2, tt = lane & 3;

  // per-thread load coords: 64 rows x 4 uint4 (32 bf16 cols) per array
  const int lr = tid >> 2, lc = tid & 3;
  const int wr = (lr >> 4) * KH + hc0 + (lr & 15);   // global W_hh row for B
  const __nv_bfloat16* srcAhi = hi_in + (size_t)lr * KH;
  const __nv_bfloat16* srcAlo = lo_in + (size_t)lr * KH;
  const __nv_bfloat16* srcBhi = g_Whh_hi + (size_t)wr * KH;
  const __nv_bfloat16* srcBlo = g_Whh_lo + (size_t)wr * KH;
  const int sOff = lr * ST_AS + lc * 8;              // bf16 elements

  auto issue = [&](int stage, int k0) {
    __nv_bfloat16* base = reinterpret_cast<__nv_bfloat16*>(smem_raw + stage * STAGE_B);
    cpa16(base + sOff,                reinterpret_cast<const uint4*>(srcAhi + k0) + lc);
    cpa16(base + 64 * ST_AS + sOff,   reinterpret_cast<const uint4*>(srcAlo + k0) + lc);
    cpa16(base + 128 * ST_AS + sOff,  reinterpret_cast<const uint4*>(srcBhi + k0) + lc);
    cpa16(base + 192 * ST_AS + sOff,  reinterpret_cast<const uint4*>(srcBlo + k0) + lc);
  };

  float acc[2][2][4];
  #pragma unroll
  for (int a = 0; a < 2; a++)
    #pragma unroll
    for (int b = 0; b < 2; b++)
      #pragma unroll
      for (int c = 0; c < 4; c++) acc[a][b][c] = 0.f;

  issue(0, 0);
  CP_COMMIT();

  for (int kt = 0; kt < KH / 32; kt++) {             // 64 stages
    if (kt + 1 < KH / 32) issue((kt + 1) & 1, (kt + 1) * 32);
    CP_COMMIT();
    CP_WAIT1();                                      // stage kt landed
    __syncthreads();                                 // visible to all threads

    const __nv_bfloat16* base =
        reinterpret_cast<const __nv_bfloat16*>(smem_raw + (kt & 1) * STAGE_B);
    const __nv_bfloat16* sAhi = base;
    const __nv_bfloat16* sAlo = base + 64 * ST_AS;
    const __nv_bfloat16* sBhi = base + 128 * ST_AS;
    const __nv_bfloat16* sBlo = base + 192 * ST_AS;

    #pragma unroll
    for (int kk = 0; kk < 32; kk += 16) {
      uint32_t Ah[2][4], Al[2][4], Bh[2][2], Bl[2][2];
      #pragma unroll
      for (int mt = 0; mt < 2; mt++) {
        const __nv_bfloat16* pa = sAhi + (wm * 32 + mt * 16 + g) * ST_AS + kk + 2 * tt;
        const __nv_bfloat16* pl = sAlo + (wm * 32 + mt * 16 + g) * ST_AS + kk + 2 * tt;
        Ah[mt][0] = *(const uint32_t*)(pa);
        Ah[mt][1] = *(const uint32_t*)(pa + 8 * ST_AS);
        Ah[mt][2] = *(const uint32_t*)(pa + 8);
        Ah[mt][3] = *(const uint32_t*)(pa + 8 * ST_AS + 8);
        Al[mt][0] = *(const uint32_t*)(pl);
        Al[mt][1] = *(const uint32_t*)(pl + 8 * ST_AS);
        Al[mt][2] = *(const uint32_t*)(pl + 8);
        Al[mt][3] = *(const uint32_t*)(pl + 8 * ST_AS + 8);
      }
      #pragma unroll
      for (int nt = 0; nt < 2; nt++) {
        const __nv_bfloat16* pb = sBhi + (wn * 16 + nt * 8 + g) * ST_AS + kk + 2 * tt;
        const __nv_bfloat16* pq = sBlo + (wn * 16 + nt * 8 + g) * ST_AS + kk + 2 * tt;
        Bh[nt][0] = *(const uint32_t*)(pb);
        Bh[nt][1] = *(const uint32_t*)(pb + 8);
        Bl[nt][0] = *(const uint32_t*)(pq);
        Bl[nt][1] = *(const uint32_t*)(pq + 8);
      }
      #pragma unroll
      for (int mt = 0; mt < 2; mt++)
        #pragma unroll
        for (int nt = 0; nt < 2; nt++) {
          mma16816(acc[mt][nt], Ah[mt][0], Ah[mt][1], Ah[mt][2], Ah[mt][3], Bh[nt][0], Bh[nt][1]);
          mma16816(acc[mt][nt], Ah[mt][0], Ah[mt][1], Ah[mt][2], Ah[mt][3], Bl[nt][0], Bl[nt][1]);
          mma16816(acc[mt][nt], Al[mt][0], Al[mt][1], Al[mt][2], Al[mt][3], Bh[nt][0], Bh[nt][1]);
        }
    }
    __syncthreads();   // reads of stage kt done before it is re-issued at kt+2
  }
  CP_WAIT0();

  // ---- epilogue: gate tile -> smem (reuse buffers), fused LSTM cell update ----
  float* sG = reinterpret_cast<float*>(smem_raw);   // 64 x 68 fp32 (17408 B)
  constexpr int GS = 68;
  #pragma unroll
  for (int mt = 0; mt < 2; mt++)
    #pragma unroll
    for (int nt = 0; nt < 2; nt++) {
      int row = wm * 32 + mt * 16 + g;
      int col = wn * 16 + nt * 8 + 2 * tt;
      sG[row * GS + col]           = acc[mt][nt][0];
      sG[row * GS + col + 1]       = acc[mt][nt][1];
      sG[(row + 8) * GS + col]     = acc[mt][nt][2];
      sG[(row + 8) * GS + col + 1] = acc[mt][nt][3];
    }
  __syncthreads();

  for (int it = tid; it < 1024; it += 256) {
    int bb = it >> 4, jj = it & 15;
    size_t xr = ((size_t)(bb * KT + t)) * KG4 + hc0 + jj;
    float ig = sG[bb * GS + jj]      + g_Xg[xr];
    float fg = sG[bb * GS + 16 + jj] + g_Xg[xr + KH];
    float gg = sG[bb * GS + 32 + jj] + g_Xg[xr + 2 * KH];
    float og = sG[bb * GS + 48 + jj] + g_Xg[xr + 3 * KH];
    float is = 1.f / (1.f + expf(-ig));
    float fs = 1.f / (1.f + expf(-fg));
    float gt = tanhf(gg);
    float os = 1.f / (1.f + expf(-og));
    int ci = bb * KH + hc0 + jj;
    float cv = fs * g_c[ci] + is * gt;
    g_c[ci] = cv;
    float hv = os * tanhf(cv);
    g_hs[((size_t)t * KB + bb) * KH + hc0 + jj] = hv;
    __nv_bfloat16 hh, hl; split2(hv, hh, hl);
    hi_out[ci] = hh; lo_out[ci] = hl;
  }
}

// ---------------------------------------------------------------------------
// poses[b,t,:] = hs[t,b,:] @ W_fc^T + b_fc  (one block per (t,b))
// ---------------------------------------------------------------------------
__global__ void fc_kernel(const float* __restrict__ Wfc, const float* __restrict__ bfc,
                          float* __restrict__ out) {
  int bt = blockIdx.x;
  int t = bt >> 6, b = bt & 63;
  const float* hrow = g_hs + ((size_t)t * KB + b) * KH;
  int tid = threadIdx.x;
  float a[KO];
  #pragma unroll
  for (int o = 0; o < KO; o++) a[o] = 0.f;
  for (int h = tid; h < KH; h += 128) {
    float v = hrow[h];
    #pragma unroll
    for (int o = 0; o < KO; o++) a[o] += v * Wfc[o * KH + h];
  }
  __shared__ float red[KO][128];
  #pragma unroll
  for (int o = 0; o < KO; o++) red[o][tid] = a[o];
  __syncthreads();
  for (int s = 64; s > 0; s >>= 1) {
    if (tid < s) {
      #pragma unroll
      for (int o = 0; o < KO; o++) red[o][tid] += red[o][tid + s];
    }
    __syncthreads();
  }
  if (tid < KO)
    out[((size_t)b * KT + t) * KO + tid] = red[tid][0] + bfc[tid];
}

// ---------------------------------------------------------------------------
// Launch: split -> mean -> init -> Xg GEMM -> 512 step kernels -> FC
// All default-stream launches; graph-capturable, allocation-free.
// ---------------------------------------------------------------------------
extern "C" void kernel_launch(void* const* d_in, const int* in_sizes, int n_in,
                              void* d_out, int out_size) {
  (void)in_sizes; (void)n_in; (void)out_size;
  const float* x    = (const float*)d_in[0];
  const float* W_ih = (const float*)d_in[1];
  const float* b_ih = (const float*)d_in[2];
  const float* W_hh = (const float*)d_in[3];
  const float* b_hh = (const float*)d_in[4];
  const float* W_h0 = (const float*)d_in[5];
  const float* b_h0 = (const float*)d_in[6];
  const float* W_c0 = (const float*)d_in[7];
  const float* b_c0 = (const float*)d_in[8];
  const float* W_fc = (const float*)d_in[9];
  const float* b_fc = (const float*)d_in[10];
  float* out = (float*)d_out;

  split_x_kernel<<<(KBT * KD) / 256, 256>>>(x);
  split_wih_kernel<<<(KG4 * KD) / 256, 256>>>(W_ih);
  split_whh_kernel<<<(KG4 * KH) / 256, 256>>>(W_hh);

  mean_kernel<<<dim3(KD / 256, KB), 256>>>(x);
  init_kernel<<<dim3(KH / 256, KB), 256>>>(W_h0, b_h0, W_c0, b_c0);

  xg_gemm_kernel<<<dim3(KG4 / 64, KBT / 128), 256>>>(b_ih, b_hh);

  for (int t = 0; t < KT; t++)
    lstm_step_kernel<<<KH / 16, 256>>>(t);

  fc_kernel<<<KBT, 128>>>(W_fc, b_fc, out);
}